// round 4
// baseline (speedup 1.0000x reference)
#include <cuda_runtime.h>
#include <cuda_bf16.h>
#include <math.h>

#define SEQ 2048
#define HIDDIM 768
#define NQH 12
#define NKVH 3
#define HDIM 64
#define QKVC 1152        // (12 + 3 + 3) * 64
#define NEXP 16
#define FFD 1536
#define NROWS (SEQ * 2)  // top-2 assignments

// ---------------- device-global scratch (no allocations allowed) ----------------
__device__ float g_xn [SEQ * HIDDIM];
__device__ float g_qkv[SEQ * QKVC];
__device__ float g_att[SEQ * HIDDIM];
__device__ float g_h  [SEQ * HIDDIM];
__device__ float g_mi [SEQ * HIDDIM];
__device__ int   g_eidx[SEQ * 2];
__device__ float g_ew  [SEQ * 2];
__device__ int   g_cnt[NEXP];
__device__ int   g_off[NEXP + 1];
__device__ int   g_cur[NEXP];
__device__ int   g_rows_tok[NROWS];
__device__ float g_rows_w [NROWS];
__device__ int   g_tok_row[SEQ * 2];
__device__ float g_hid[(size_t)NROWS * FFD];     // 25 MB
__device__ float g_yex[(size_t)NROWS * HIDDIM];  // 12.6 MB

// ---------------- RMSNorm ----------------
__global__ void rmsnorm_kernel(const float* __restrict__ x, const float* __restrict__ w,
                               float* __restrict__ out) {
    int t = blockIdx.x;
    __shared__ float red[256];
    const float* xr = x + (size_t)t * HIDDIM;
    float ss = 0.f;
    for (int i = threadIdx.x; i < HIDDIM; i += 256) { float v = xr[i]; ss += v * v; }
    red[threadIdx.x] = ss;
    __syncthreads();
    for (int s2 = 128; s2 > 0; s2 >>= 1) {
        if (threadIdx.x < s2) red[threadIdx.x] += red[threadIdx.x + s2];
        __syncthreads();
    }
    float inv = rsqrtf(red[0] * (1.0f / HIDDIM) + 1e-6f);
    for (int i = threadIdx.x; i < HIDDIM; i += 256)
        out[(size_t)t * HIDDIM + i] = xr[i] * inv * w[i];
}

// ---------------- generic 64x64x16 fp32 GEMM (optionally + residual) ----------------
template <bool ADD_RES>
__global__ __launch_bounds__(256) void gemm64(const float* __restrict__ A,
                                              const float* __restrict__ B,
                                              const float* __restrict__ Res,
                                              float* __restrict__ C,
                                              int M, int N, int K) {
    __shared__ float As[16][64];
    __shared__ float Bs[16][64];
    const int m0 = blockIdx.y * 64, n0 = blockIdx.x * 64;
    const int tid = threadIdx.x;
    const int tm = (tid & 15) * 4, tn = (tid >> 4) * 4;
    const int arow = tid >> 2, akk = (tid & 3) * 4;
    const int bk = tid >> 4, bn = (tid & 15) * 4;
    float acc[4][4];
#pragma unroll
    for (int i = 0; i < 4; i++)
#pragma unroll
        for (int j = 0; j < 4; j++) acc[i][j] = 0.f;

    const float* Aptr = A + (size_t)(m0 + arow) * K + akk;
    const float* Bptr = B + (size_t)bk * N + n0 + bn;

    for (int k0 = 0; k0 < K; k0 += 16) {
        float4 av = *(const float4*)(Aptr + k0);
        As[akk + 0][arow] = av.x; As[akk + 1][arow] = av.y;
        As[akk + 2][arow] = av.z; As[akk + 3][arow] = av.w;
        *(float4*)&Bs[bk][bn] = *(const float4*)(Bptr + (size_t)k0 * N);
        __syncthreads();
#pragma unroll
        for (int k = 0; k < 16; k++) {
            float4 a = *(const float4*)&As[k][tm];
            float4 b = *(const float4*)&Bs[k][tn];
            acc[0][0] += a.x * b.x; acc[0][1] += a.x * b.y; acc[0][2] += a.x * b.z; acc[0][3] += a.x * b.w;
            acc[1][0] += a.y * b.x; acc[1][1] += a.y * b.y; acc[1][2] += a.y * b.z; acc[1][3] += a.y * b.w;
            acc[2][0] += a.z * b.x; acc[2][1] += a.z * b.y; acc[2][2] += a.z * b.z; acc[2][3] += a.z * b.w;
            acc[3][0] += a.w * b.x; acc[3][1] += a.w * b.y; acc[3][2] += a.w * b.z; acc[3][3] += a.w * b.w;
        }
        __syncthreads();
    }
#pragma unroll
    for (int i = 0; i < 4; i++) {
        int row = m0 + tm + i;
        float4 v = make_float4(acc[i][0], acc[i][1], acc[i][2], acc[i][3]);
        if (ADD_RES) {
            float4 rr = *(const float4*)&Res[(size_t)row * N + n0 + tn];
            v.x += rr.x; v.y += rr.y; v.z += rr.z; v.w += rr.w;
        }
        *(float4*)&C[(size_t)row * N + n0 + tn] = v;
    }
}

// ---------------- RoPE (in-place on q and k inside qkv) ----------------
__global__ void rope_kernel(float* __restrict__ qkv) {
    int s = blockIdx.x;
    int t = threadIdx.x;
    if (t >= (NQH + NKVH) * (HDIM / 2)) return;
    int hh = t / 32, p = t & 31;
    int col = (hh < NQH) ? hh * HDIM : (NQH * HDIM + (hh - NQH) * HDIM);
    float expo = (float)(2 * p) * (1.0f / HDIM);
    float inv = powf(10000.0f, -expo);
    float ang = (float)s * inv;
    float c, sn;
    sincosf(ang, &sn, &c);
    float* base = qkv + (size_t)s * QKVC + col;
    float x0 = base[2 * p], x1 = base[2 * p + 1];
    base[2 * p]     = x0 * c - x1 * sn;
    base[2 * p + 1] = x0 * sn + x1 * c;
}

// ---------------- causal flash attention (fp32, 64x64 tiles) ----------------
__global__ __launch_bounds__(256) void attn_kernel(const float* __restrict__ qkv,
                                                   float* __restrict__ out) {
    extern __shared__ float sm[];
    float* QsT  = sm;                  // [64][68]  QsT[d*68+m]
    float* Kst  = QsT + 64 * 68;       // [64][68]  Kst[d*68+c]
    float* Vs   = Kst + 64 * 68;       // [64][64]  Vs[c*64+d]
    float* Ss   = Vs + 64 * 64;        // [64][68]  Ss[r*68+c]
    float* rowM = Ss + 64 * 68;        // [64]
    float* rowL = rowM + 64;           // [64]
    float* partM = rowL + 64;          // [4][64]
    float* partL = partM + 256;        // [4][64]

    const int h = blockIdx.y, kvh = h >> 2;  // REP = 4
    const int q0 = blockIdx.x * 64;
    const int tid = threadIdx.x;
    const int r = tid & 63;
    const int cg = tid >> 6;

    float accO[16];
#pragma unroll
    for (int j = 0; j < 16; j++) accO[j] = 0.f;

    for (int i = tid; i < 4096; i += 256) {
        int m = i >> 6, d = i & 63;
        QsT[d * 68 + m] = qkv[(size_t)(q0 + m) * QKVC + h * HDIM + d] * 0.125f;
    }
    if (tid < 64) { rowM[tid] = -1e30f; rowL[tid] = 0.f; }
    __syncthreads();

    for (int kt = 0; kt <= (int)blockIdx.x; ++kt) {
        const int k0 = kt * 64;
        for (int i = tid; i < 4096; i += 256) {
            int c = i >> 6, d = i & 63;
            const float* row = qkv + (size_t)(k0 + c) * QKVC;
            Kst[d * 68 + c] = row[NQH * HDIM + kvh * HDIM + d];
            Vs[c * 64 + d]  = row[(NQH + NKVH) * HDIM + kvh * HDIM + d];
        }
        __syncthreads();

        float s[16];
#pragma unroll
        for (int j = 0; j < 16; j++) s[j] = 0.f;
#pragma unroll 4
        for (int d = 0; d < 64; ++d) {
            float qv = QsT[d * 68 + r];
            const float* kr = &Kst[d * 68 + cg * 16];
            float4 ka = *(const float4*)(kr);
            float4 kb = *(const float4*)(kr + 4);
            float4 kc = *(const float4*)(kr + 8);
            float4 kd = *(const float4*)(kr + 12);
            s[0]  += qv * ka.x; s[1]  += qv * ka.y; s[2]  += qv * ka.z; s[3]  += qv * ka.w;
            s[4]  += qv * kb.x; s[5]  += qv * kb.y; s[6]  += qv * kb.z; s[7]  += qv * kb.w;
            s[8]  += qv * kc.x; s[9]  += qv * kc.y; s[10] += qv * kc.z; s[11] += qv * kc.w;
            s[12] += qv * kd.x; s[13] += qv * kd.y; s[14] += qv * kd.z; s[15] += qv * kd.w;
        }

        bool diag = (kt == (int)blockIdx.x);
        float lmax = -1e30f;
#pragma unroll
        for (int j = 0; j < 16; j++) {
            int c = cg * 16 + j;
            if (diag && (k0 + c > q0 + r)) s[j] = -1e30f;
            lmax = fmaxf(lmax, s[j]);
        }
        partM[cg * 64 + r] = lmax;
        __syncthreads();

        float m_old = rowM[r];
        float m_new = fmaxf(m_old,
                      fmaxf(fmaxf(partM[r], partM[64 + r]),
                            fmaxf(partM[128 + r], partM[192 + r])));
        float alpha = __expf(m_old - m_new);
        float lsum = 0.f;
#pragma unroll
        for (int j = 0; j < 16; j++) {
            float p = __expf(s[j] - m_new);
            Ss[r * 68 + cg * 16 + j] = p;
            lsum += p;
        }
        partL[cg * 64 + r] = lsum;
#pragma unroll
        for (int j = 0; j < 16; j++) accO[j] *= alpha;
        __syncthreads();

        if (cg == 0) {
            rowM[r] = m_new;
            rowL[r] = rowL[r] * alpha + partL[r] + partL[64 + r] + partL[128 + r] + partL[192 + r];
        }

#pragma unroll 4
        for (int c = 0; c < 64; c++) {
            float pv = Ss[r * 68 + c];
            const float* vr = &Vs[c * 64 + cg * 16];
            float4 va = *(const float4*)(vr);
            float4 vb = *(const float4*)(vr + 4);
            float4 vc = *(const float4*)(vr + 8);
            float4 vd = *(const float4*)(vr + 12);
            accO[0]  += pv * va.x; accO[1]  += pv * va.y; accO[2]  += pv * va.z; accO[3]  += pv * va.w;
            accO[4]  += pv * vb.x; accO[5]  += pv * vb.y; accO[6]  += pv * vb.z; accO[7]  += pv * vb.w;
            accO[8]  += pv * vc.x; accO[9]  += pv * vc.y; accO[10] += pv * vc.z; accO[11] += pv * vc.w;
            accO[12] += pv * vd.x; accO[13] += pv * vd.y; accO[14] += pv * vd.z; accO[15] += pv * vd.w;
        }
        __syncthreads();
    }

    float inv = 1.f / rowL[r];
    float* orow = out + (size_t)(q0 + r) * (NQH * HDIM) + h * HDIM + cg * 16;
#pragma unroll
    for (int j = 0; j < 16; j++) orow[j] = accO[j] * inv;
}

// ---------------- router: top-2 of logits, pairwise-softmax weights ----------------
__global__ void router_kernel(const float* __restrict__ x, const float* __restrict__ wr) {
    int t = blockIdx.x;
    __shared__ float xr[HIDDIM];
    __shared__ float lg[NEXP];
    for (int i = threadIdx.x; i < HIDDIM; i += blockDim.x) xr[i] = x[(size_t)t * HIDDIM + i];
    __syncthreads();
    if (threadIdx.x < NEXP) {
        float a = 0.f;
        for (int k = 0; k < HIDDIM; k++) a += xr[k] * wr[k * NEXP + threadIdx.x];
        lg[threadIdx.x] = a;
    }
    __syncthreads();
    if (threadIdx.x == 0) {
        int i0 = 0; float l0 = lg[0];
        for (int e = 1; e < NEXP; e++) if (lg[e] > l0) { l0 = lg[e]; i0 = e; }
        int i1 = (i0 == 0) ? 1 : 0; float l1 = lg[i1];
        for (int e = 0; e < NEXP; e++) if (e != i0 && lg[e] > l1) { l1 = lg[e]; i1 = e; }
        float w0 = 1.f / (1.f + __expf(l1 - l0));
        g_eidx[2 * t] = i0; g_eidx[2 * t + 1] = i1;
        g_ew[2 * t] = w0;   g_ew[2 * t + 1] = 1.f - w0;
        atomicAdd(&g_cnt[i0], 1);
        atomicAdd(&g_cnt[i1], 1);
    }
}

__global__ void zero_cnt_kernel() { if (threadIdx.x < NEXP) g_cnt[threadIdx.x] = 0; }

__global__ void prefix_kernel() {
    if (threadIdx.x == 0) {
        int acc = 0;
        for (int e = 0; e < NEXP; e++) { g_off[e] = acc; g_cur[e] = acc; acc += g_cnt[e]; }
        g_off[NEXP] = acc;
    }
}

__global__ void scatter_kernel() {
    int t = blockIdx.x * blockDim.x + threadIdx.x;
    if (t >= SEQ) return;
    for (int j = 0; j < 2; j++) {
        int e = g_eidx[2 * t + j];
        int pos = atomicAdd(&g_cur[e], 1);
        g_rows_tok[pos] = t;
        g_rows_w[pos] = g_ew[2 * t + j];
        g_tok_row[2 * t + j] = pos;
    }
}

// ---------------- MoE GEMM1: gathered x @ w_gate_up[e], fused SiLU*up ----------------
__global__ __launch_bounds__(256) void moe_gemm1(const float* __restrict__ x,
                                                 const float* __restrict__ wgu) {
    const int e = blockIdx.z;
    const int off = g_off[e];
    const int cnt = g_off[e + 1] - off;
    const int m0 = blockIdx.y * 64;
    if (m0 >= cnt) return;
    const int n0 = blockIdx.x * 64;

    __shared__ float As[16][64];
    __shared__ float Bg[16][64];
    __shared__ float Bu[16][64];
    __shared__ int toks[64];

    const int tid = threadIdx.x;
    if (tid < 64) {
        int rr = m0 + tid;
        toks[tid] = (rr < cnt) ? g_rows_tok[off + rr] : g_rows_tok[off];
    }
    __syncthreads();

    const int tm = (tid & 15) * 4, tn = (tid >> 4) * 4;
    const int arow = tid >> 2, akk = (tid & 3) * 4;
    const int bk = tid >> 4, bn = (tid & 15) * 4;
    const int atok = toks[arow];
    const float* Aptr = x + (size_t)atok * HIDDIM + akk;
    const float* Wb = wgu + (size_t)e * HIDDIM * (2 * FFD) + (size_t)bk * (2 * FFD) + n0 + bn;

    float ag[4][4], au[4][4];
#pragma unroll
    for (int i = 0; i < 4; i++)
#pragma unroll
        for (int j = 0; j < 4; j++) { ag[i][j] = 0.f; au[i][j] = 0.f; }

    for (int k0 = 0; k0 < HIDDIM; k0 += 16) {
        float4 av = *(const float4*)(Aptr + k0);
        As[akk + 0][arow] = av.x; As[akk + 1][arow] = av.y;
        As[akk + 2][arow] = av.z; As[akk + 3][arow] = av.w;
        const float* wrow = Wb + (size_t)k0 * (2 * FFD);
        *(float4*)&Bg[bk][bn] = *(const float4*)(wrow);
        *(float4*)&Bu[bk][bn] = *(const float4*)(wrow + FFD);
        __syncthreads();
#pragma unroll
        for (int k = 0; k < 16; k++) {
            float4 a = *(const float4*)&As[k][tm];
            float4 g = *(const float4*)&Bg[k][tn];
            float4 u = *(const float4*)&Bu[k][tn];
            ag[0][0] += a.x * g.x; ag[0][1] += a.x * g.y; ag[0][2] += a.x * g.z; ag[0][3] += a.x * g.w;
            ag[1][0] += a.y * g.x; ag[1][1] += a.y * g.y; ag[1][2] += a.y * g.z; ag[1][3] += a.y * g.w;
            ag[2][0] += a.z * g.x; ag[2][1] += a.z * g.y; ag[2][2] += a.z * g.z; ag[2][3] += a.z * g.w;
            ag[3][0] += a.w * g.x; ag[3][1] += a.w * g.y; ag[3][2] += a.w * g.z; ag[3][3] += a.w * g.w;
            au[0][0] += a.x * u.x; au[0][1] += a.x * u.y; au[0][2] += a.x * u.z; au[0][3] += a.x * u.w;
            au[1][0] += a.y * u.x; au[1][1] += a.y * u.y; au[1][2] += a.y * u.z; au[1][3] += a.y * u.w;
            au[2][0] += a.z * u.x; au[2][1] += a.z * u.y; au[2][2] += a.z * u.z; au[2][3] += a.z * u.w;
            au[3][0] += a.w * u.x; au[3][1] += a.w * u.y; au[3][2] += a.w * u.z; au[3][3] += a.w * u.w;
        }
        __syncthreads();
    }
#pragma unroll
    for (int i = 0; i < 4; i++) {
        int rr = m0 + tm + i;
        if (rr >= cnt) continue;
        float4 v;
        float g0 = ag[i][0], g1 = ag[i][1], g2 = ag[i][2], g3 = ag[i][3];
        v.x = g0 / (1.f + __expf(-g0)) * au[i][0];
        v.y = g1 / (1.f + __expf(-g1)) * au[i][1];
        v.z = g2 / (1.f + __expf(-g2)) * au[i][2];
        v.w = g3 / (1.f + __expf(-g3)) * au[i][3];
        *(float4*)&g_hid[(size_t)(off + rr) * FFD + n0 + tn] = v;
    }
}

// ---------------- MoE GEMM2: hidden @ w_down[e], scaled by combine weight ----------------
__global__ __launch_bounds__(256) void moe_gemm2(const float* __restrict__ wd) {
    const int e = blockIdx.z;
    const int off = g_off[e];
    const int cnt = g_off[e + 1] - off;
    const int m0 = blockIdx.y * 64;
    if (m0 >= cnt) return;
    const int n0 = blockIdx.x * 64;

    __shared__ float As[16][64];
    __shared__ float Bs[16][64];

    const int tid = threadIdx.x;
    const int tm = (tid & 15) * 4, tn = (tid >> 4) * 4;
    const int arow = tid >> 2, akk = (tid & 3) * 4;
    const int bk = tid >> 4, bn = (tid & 15) * 4;

    int rrow = m0 + arow;
    if (rrow >= cnt) rrow = 0;
    const float* Aptr = g_hid + (size_t)(off + rrow) * FFD + akk;
    const float* Bptr = wd + (size_t)e * FFD * HIDDIM + (size_t)bk * HIDDIM + n0 + bn;

    float acc[4][4];
#pragma unroll
    for (int i = 0; i < 4; i++)
#pragma unroll
        for (int j = 0; j < 4; j++) acc[i][j] = 0.f;

    for (int k0 = 0; k0 < FFD; k0 += 16) {
        float4 av = *(const float4*)(Aptr + k0);
        As[akk + 0][arow] = av.x; As[akk + 1][arow] = av.y;
        As[akk + 2][arow] = av.z; As[akk + 3][arow] = av.w;
        *(float4*)&Bs[bk][bn] = *(const float4*)(Bptr + (size_t)k0 * HIDDIM);
        __syncthreads();
#pragma unroll
        for (int k = 0; k < 16; k++) {
            float4 a = *(const float4*)&As[k][tm];
            float4 b = *(const float4*)&Bs[k][tn];
            acc[0][0] += a.x * b.x; acc[0][1] += a.x * b.y; acc[0][2] += a.x * b.z; acc[0][3] += a.x * b.w;
            acc[1][0] += a.y * b.x; acc[1][1] += a.y * b.y; acc[1][2] += a.y * b.z; acc[1][3] += a.y * b.w;
            acc[2][0] += a.z * b.x; acc[2][1] += a.z * b.y; acc[2][2] += a.z * b.z; acc[2][3] += a.z * b.w;
            acc[3][0] += a.w * b.x; acc[3][1] += a.w * b.y; acc[3][2] += a.w * b.z; acc[3][3] += a.w * b.w;
        }
        __syncthreads();
    }
#pragma unroll
    for (int i = 0; i < 4; i++) {
        int rr = m0 + tm + i;
        if (rr >= cnt) continue;
        float w = g_rows_w[off + rr];
        float4 v = make_float4(acc[i][0] * w, acc[i][1] * w, acc[i][2] * w, acc[i][3] * w);
        *(float4*)&g_yex[(size_t)(off + rr) * HIDDIM + n0 + tn] = v;
    }
}

// ---------------- final combine: out = h + y(expert0) + y(expert1) ----------------
__global__ void combine_kernel(float* __restrict__ out) {
    int t = blockIdx.x;
    int r0 = g_tok_row[2 * t], r1 = g_tok_row[2 * t + 1];
    const float* hr = g_h + (size_t)t * HIDDIM;
    const float* y0 = g_yex + (size_t)r0 * HIDDIM;
    const float* y1 = g_yex + (size_t)r1 * HIDDIM;
    for (int d = threadIdx.x; d < HIDDIM; d += blockDim.x)
        out[(size_t)t * HIDDIM + d] = hr[d] + y0[d] + y1[d];
}

// ---------------- launch ----------------
extern "C" void kernel_launch(void* const* d_in, const int* in_sizes, int n_in,
                              void* d_out, int out_size) {
    const float* x    = (const float*)d_in[0];
    const float* n1w  = (const float*)d_in[1];
    const float* wqkv = (const float*)d_in[2];
    const float* wout = (const float*)d_in[3];
    const float* n2w  = (const float*)d_in[4];
    const float* wr   = (const float*)d_in[5];
    const float* wgu  = (const float*)d_in[6];
    const float* wd   = (const float*)d_in[7];
    float* out = (float*)d_out;

    void *p_xn, *p_qkv, *p_att, *p_h, *p_mi;
    cudaGetSymbolAddress(&p_xn, g_xn);
    cudaGetSymbolAddress(&p_qkv, g_qkv);
    cudaGetSymbolAddress(&p_att, g_att);
    cudaGetSymbolAddress(&p_h, g_h);
    cudaGetSymbolAddress(&p_mi, g_mi);

    // 1. pre-attention RMSNorm
    rmsnorm_kernel<<<SEQ, 256>>>(x, n1w, (float*)p_xn);

    // 2. QKV projection
    {
        dim3 grid(QKVC / 64, SEQ / 64);
        gemm64<false><<<grid, 256>>>((const float*)p_xn, wqkv, nullptr, (float*)p_qkv,
                                     SEQ, QKVC, HIDDIM);
    }

    // 3. RoPE on q and k
    rope_kernel<<<SEQ, 512>>>((float*)p_qkv);

    // 4. causal flash attention
    {
        dim3 grid(SEQ / 64, NQH);
        size_t smem = (size_t)(64 * 68 * 3 + 64 * 64 + 64 + 64 + 256 + 256) * sizeof(float);
        cudaFuncSetAttribute(attn_kernel, cudaFuncAttributeMaxDynamicSharedMemorySize, (int)smem);
        attn_kernel<<<grid, 256, smem>>>((const float*)p_qkv, (float*)p_att);
    }

    // 5. output projection + residual
    {
        dim3 grid(HIDDIM / 64, SEQ / 64);
        gemm64<true><<<grid, 256>>>((const float*)p_att, wout, x, (float*)p_h,
                                    SEQ, HIDDIM, HIDDIM);
    }

    // 6. pre-MoE RMSNorm
    rmsnorm_kernel<<<SEQ, 256>>>((const float*)p_h, n2w, (float*)p_mi);

    // 7. routing: top-2, counts, offsets, scatter into per-expert row lists
    zero_cnt_kernel<<<1, 32>>>();
    router_kernel<<<SEQ, 128>>>((const float*)p_mi, wr);
    prefix_kernel<<<1, 1>>>();
    scatter_kernel<<<(SEQ + 255) / 256, 256>>>();

    // 8. expert gate/up GEMM + fused SiLU
    {
        dim3 grid(FFD / 64, NROWS / 64, NEXP);
        moe_gemm1<<<grid, 256>>>((const float*)p_mi, wgu);
    }

    // 9. expert down GEMM (scaled by combine weight)
    {
        dim3 grid(HIDDIM / 64, NROWS / 64, NEXP);
        moe_gemm2<<<grid, 256>>>(wd);
    }

    // 10. combine: out = h + sum of the token's 2 expert outputs
    combine_kernel<<<SEQ, 256>>>(out);
}